// round 16
// baseline (speedup 1.0000x reference)
#include <cuda_runtime.h>
#include <cuda_fp16.h>
#include <math.h>
#include <stdint.h>

#define B_  4
#define S_  2048
#define D_  1024
#define M_TOT (B_ * S_)   // 8192

typedef __half fp16;

// ---------------- scratch (allocation-free rule: __device__ globals) ----------------
__device__ fp16  g_x0[(size_t)M_TOT * D_], g_x1[(size_t)M_TOT * D_];
__device__ fp16  g_wq0[(size_t)D_ * D_], g_wq1[(size_t)D_ * D_];
__device__ fp16  g_wk0[(size_t)D_ * D_], g_wk1[(size_t)D_ * D_];
__device__ fp16  g_wv0[(size_t)D_ * D_], g_wv1[(size_t)D_ * D_];
__device__ fp16  g_q0[(size_t)M_TOT * D_], g_q1[(size_t)M_TOT * D_];
__device__ fp16  g_k0[(size_t)M_TOT * D_], g_k1[(size_t)M_TOT * D_];
__device__ fp16  g_v0[(size_t)M_TOT * D_], g_v1[(size_t)M_TOT * D_];
__device__ fp16  g_vT0[(size_t)M_TOT * D_];                              // [B][D,S]
__device__ float g_s[(size_t)B_ * S_ * S_];                              // scores fp32
__device__ fp16  g_w0[(size_t)B_ * S_ * S_];                             // softmax weights fp16

// ---------------- helpers ----------------
__device__ __forceinline__ uint32_t smem_u32(const void* p) {
    uint32_t a;
    asm("{ .reg .u64 t; cvta.to.shared.u64 t, %1; cvt.u32.u64 %0, t; }" : "=r"(a) : "l"(p));
    return a;
}
__device__ __forceinline__ void cp_async16(uint32_t dst, const void* src) {
    asm volatile("cp.async.cg.shared.global [%0], [%1], 16;" :: "r"(dst), "l"(src) : "memory");
}
__device__ __forceinline__ void cp_commit() { asm volatile("cp.async.commit_group;" ::: "memory"); }
__device__ __forceinline__ void cp_wait0()  { asm volatile("cp.async.wait_group 0;"  ::: "memory"); }

__device__ __forceinline__ void ldsm_x4(uint32_t* r, uint32_t addr) {
    asm volatile("ldmatrix.sync.aligned.m8n8.x4.shared.b16 {%0,%1,%2,%3}, [%4];"
        : "=r"(r[0]), "=r"(r[1]), "=r"(r[2]), "=r"(r[3]) : "r"(addr));
}
__device__ __forceinline__ void ldsm_x2(uint32_t* r, uint32_t addr) {
    asm volatile("ldmatrix.sync.aligned.m8n8.x2.shared.b16 {%0,%1}, [%2];"
        : "=r"(r[0]), "=r"(r[1]) : "r"(addr));
}
__device__ __forceinline__ void mma_h(float* c, const uint32_t* a, const uint32_t* b) {
    asm volatile(
        "mma.sync.aligned.m16n8k16.row.col.f32.f16.f16.f32 "
        "{%0,%1,%2,%3}, {%4,%5,%6,%7}, {%8,%9}, {%0,%1,%2,%3};"
        : "+f"(c[0]), "+f"(c[1]), "+f"(c[2]), "+f"(c[3])
        : "r"(a[0]), "r"(a[1]), "r"(a[2]), "r"(a[3]), "r"(b[0]), "r"(b[1]));
}
__device__ __forceinline__ uint32_t pack2h(fp16 a, fp16 b) {
    uint32_t u; fp16* p = (fp16*)&u; p[0] = a; p[1] = b; return u;
}

// Swizzled tile: 128 logical rows x 64 B (one GBK=32 K-slice of fp16).
// Rows packed pairwise into 64 storage rows of 128 B, then SW128 XOR.
#define SWZ128(x) ((x) ^ (((x) >> 3) & 0x70))
__device__ __forceinline__ uint32_t tile_off(uint32_t row, uint32_t colb) {
    return SWZ128(((row & 63u) << 7) + ((row >> 6) << 6) + colb);
}

// ---------------- GEMM: C[M,N] = sum_{i<SA, j<SB, i+j<=TMAX} Ai[M,K] * Bj[N,K]^T ----
// mode 0: fp32 C ; mode 1: 2-way fp16 (C0,C1)
// zmode 0: blockIdx.z = batch (strides sA/sB/sC)
// zmode 1: blockIdx.z in {0,1,2} selects B/C set a/b/c  [QKV fusion]
#define GBM 128
#define GBN 128
#define GBK 32
#define TILE_BYTES 8192

template<int SA, int SB, int TMAX>
__global__ __launch_bounds__(256, 2) void mma_gemm_h(
    const fp16* __restrict__ A0, const fp16* __restrict__ A1,
    const fp16* Ba0, const fp16* Ba1, const fp16* Bb0, const fp16* Bb1,
    const fp16* Bc0, const fp16* Bc1,
    float* C, fp16* Ca0, fp16* Ca1, fp16* Cb0, fp16* Cb1, fp16* Cc0, fp16* Cc1,
    int M, int N, int K, long sA, long sB, long sC, int mode, int zmode)
{
    constexpr int NTILE = SA + SB;
    constexpr int STAGE_BYTES = NTILE * TILE_BYTES;
    extern __shared__ char sm[];
    const uint32_t sbase = smem_u32(sm);

    const int tid  = threadIdx.x;
    const int wid  = tid >> 5;
    const int lane = tid & 31;
    const int gid  = lane >> 2;
    const int tig  = lane & 3;

    const fp16* B0 = Ba0; const fp16* B1 = Ba1;
    fp16* C0 = Ca0; fp16* C1 = Ca1;
    if (zmode == 1) {
        if (blockIdx.z == 1)      { B0 = Bb0; B1 = Bb1; C0 = Cb0; C1 = Cb1; }
        else if (blockIdx.z == 2) { B0 = Bc0; B1 = Bc1; C0 = Cc0; C1 = Cc1; }
    }
    const long zb = (zmode == 0) ? (long)blockIdx.z : 0;

    const int by = blockIdx.y * GBM;
    const int bx = blockIdx.x * GBN;

    const fp16* srcs[NTILE];
    srcs[0] = A0 + zb * sA + (long)by * K;
    if (SA > 1) srcs[1] = A1 + zb * sA + (long)by * K;
    srcs[SA] = B0 + zb * sB + (long)bx * K;
    if (SB > 1) srcs[SA + 1] = B1 + zb * sB + (long)bx * K;

    const int NT = K / GBK;

    auto load_stage = [&](int st, int kt) {
        #pragma unroll
        for (int t = 0; t < NTILE; t++) {
            const char* sp = (const char*)srcs[t] + kt * 64;
            uint32_t db = sbase + st * STAGE_BYTES + t * TILE_BYTES;
            #pragma unroll
            for (int p = 0; p < 2; p++) {
                int idx = p * 256 + tid;       // 0..511
                uint32_t row = idx >> 2;
                uint32_t c   = idx & 3;
                cp_async16(db + tile_off(row, c << 4), sp + (long)row * K * 2 + c * 16);
            }
        }
        cp_commit();
    };

    const int wm = (wid & 1) * 64;
    const int wn = (wid >> 1) * 32;

    float acc[4][4][4] = {};

    load_stage(0, 0);

    for (int kt = 0; kt < NT; kt++) {
        cp_wait0();
        __syncthreads();
        if (kt + 1 < NT) load_stage((kt + 1) & 1, kt + 1);

        uint32_t abase = sbase + (kt & 1) * STAGE_BYTES;
        #pragma unroll
        for (int ks = 0; ks < GBK; ks += 16) {
            // B fragments upfront
            uint32_t b[SB][4][2];
            #pragma unroll
            for (int nt = 0; nt < 4; nt++) {
                uint32_t r = wn + nt * 8 + (lane & 7);
                uint32_t cb = ((ks >> 3) + ((lane >> 3) & 1)) << 4;
                uint32_t rb = abase + SA * TILE_BYTES + tile_off(r, cb);
                #pragma unroll
                for (int s = 0; s < SB; s++)
                    ldsm_x2(b[s][nt], rb + s * TILE_BYTES);
            }
            // A per mt, then MMAs
            #pragma unroll
            for (int mt = 0; mt < 4; mt++) {
                uint32_t a[SA][4];
                uint32_t r = wm + mt * 16 + (lane & 15);
                uint32_t cb = ((ks >> 3) + (lane >> 4)) << 4;
                uint32_t ra = abase + tile_off(r, cb);
                #pragma unroll
                for (int s = 0; s < SA; s++)
                    ldsm_x4(a[s], ra + s * TILE_BYTES);
                #pragma unroll
                for (int nt = 0; nt < 4; nt++) {
                    #pragma unroll
                    for (int i = 0; i < SA; i++)
                        #pragma unroll
                        for (int j = 0; j < SB; j++)
                            if (i + j <= TMAX)
                                mma_h(acc[mt][nt], a[i], b[j][nt]);
                }
            }
        }
        __syncthreads();
    }

    // epilogue
    #pragma unroll
    for (int mt = 0; mt < 4; mt++) {
        #pragma unroll
        for (int nt = 0; nt < 4; nt++) {
            int col = bx + wn + nt * 8 + 2 * tig;
            #pragma unroll
            for (int h = 0; h < 2; h++) {
                int row = by + wm + mt * 16 + gid + h * 8;
                float v0 = acc[mt][nt][2 * h + 0];
                float v1 = acc[mt][nt][2 * h + 1];
                if (mode == 0) {
                    *(float2*)(C + zb * sC + (long)row * N + col) = make_float2(v0, v1);
                } else {
                    long base = (long)row * N + col;
                    fp16 h0 = __float2half_rn(v0);
                    fp16 h1 = __float2half_rn(v1);
                    fp16 l0 = __float2half_rn(v0 - __half2float(h0));
                    fp16 l1 = __float2half_rn(v1 - __half2float(h1));
                    *(uint32_t*)(C0 + base) = pack2h(h0, h1);
                    *(uint32_t*)(C1 + base) = pack2h(l0, l1);
                }
            }
        }
    }
}

// ---------------- split x: fp32 -> 2-way fp16 ----------------
__global__ __launch_bounds__(256) void split_x(const float* __restrict__ in,
        fp16* __restrict__ p0, fp16* __restrict__ p1, long n)
{
    long i = ((long)blockIdx.x * 256 + threadIdx.x) * 4;
    if (i >= n) return;
    float4 v = *(const float4*)(in + i);
    float vv[4] = {v.x, v.y, v.z, v.w};
    fp16 h[4], l[4];
    #pragma unroll
    for (int j = 0; j < 4; j++) {
        h[j] = __float2half_rn(vv[j]);
        l[j] = __float2half_rn(vv[j] - __half2float(h[j]));
    }
    *(uint32_t*)(p0 + i) = pack2h(h[0], h[1]); *(uint32_t*)(p0 + i + 2) = pack2h(h[2], h[3]);
    *(uint32_t*)(p1 + i) = pack2h(l[0], l[1]); *(uint32_t*)(p1 + i + 2) = pack2h(l[2], l[3]);
}

// ---------------- split + transpose: fp32 [K,N] -> 2-way fp16 [N,K] ----------------
__global__ __launch_bounds__(256) void splitT2h_f32(const float* __restrict__ in,
        fp16* __restrict__ o0, fp16* __restrict__ o1, int Kd, int Nd)
{
    __shared__ float t[32][33];
    int tx = threadIdx.x & 31, ty = threadIdx.x >> 5;
    int c0 = blockIdx.x * 32, r0 = blockIdx.y * 32;
    #pragma unroll
    for (int j = 0; j < 4; j++)
        t[ty + j * 8][tx] = in[(long)(r0 + ty + j * 8) * Nd + c0 + tx];
    __syncthreads();
    #pragma unroll
    for (int j = 0; j < 4; j++) {
        float v = t[tx][ty + j * 8];
        fp16 h = __float2half_rn(v);
        fp16 l = __float2half_rn(v - __half2float(h));
        long o = (long)(c0 + ty + j * 8) * Kd + r0 + tx;
        o0[o] = h; o1[o] = l;
    }
}

// ---------------- batched fp16 transpose: [B][S,D] -> [B][D,S]  (z = batch) ----------
__global__ __launch_bounds__(256) void transpose_fp16(const fp16* __restrict__ in,
                                                      fp16* __restrict__ out)
{
    __shared__ fp16 t[32][33];
    int b = blockIdx.z;
    in  += (long)b * S_ * D_;
    out += (long)b * S_ * D_;
    int tx = threadIdx.x & 31, ty = threadIdx.x >> 5;
    int c0 = blockIdx.x * 32, r0 = blockIdx.y * 32;
    #pragma unroll
    for (int j = 0; j < 4; j++)
        t[ty + j * 8][tx] = in[(long)(r0 + ty + j * 8) * D_ + c0 + tx];
    __syncthreads();
    #pragma unroll
    for (int j = 0; j < 4; j++)
        out[(long)(c0 + ty + j * 8) * S_ + r0 + tx] = t[tx][ty + j * 8];
}

// ---------------- softmax: fp32 scores row -> single fp16 weights ----------------
__global__ __launch_bounds__(256) void softmax_rows(const float* __restrict__ Sp,
                                                    fp16* __restrict__ W0)
{
    const float* p = Sp + (long)blockIdx.x * S_;
    fp16* p0 = W0 + (long)blockIdx.x * S_;
    const int tid = threadIdx.x;
    const int PER = S_ / 256;

    float vals[PER];
    float lmax = -INFINITY;
    #pragma unroll
    for (int i = 0; i < PER; i++) {
        vals[i] = p[tid + i * 256];
        lmax = fmaxf(lmax, vals[i]);
    }
    __shared__ float red[8];
    #pragma unroll
    for (int o = 16; o; o >>= 1) lmax = fmaxf(lmax, __shfl_xor_sync(0xFFFFFFFFu, lmax, o));
    if ((tid & 31) == 0) red[tid >> 5] = lmax;
    __syncthreads();
    float m = red[0];
    #pragma unroll
    for (int w = 1; w < 8; w++) m = fmaxf(m, red[w]);
    __syncthreads();

    float lsum = 0.f;
    #pragma unroll
    for (int i = 0; i < PER; i++) { vals[i] = expf(vals[i] - m); lsum += vals[i]; }
    #pragma unroll
    for (int o = 16; o; o >>= 1) lsum += __shfl_xor_sync(0xFFFFFFFFu, lsum, o);
    if ((tid & 31) == 0) red[tid >> 5] = lsum;
    __syncthreads();
    float s = 0.f;
    #pragma unroll
    for (int w = 0; w < 8; w++) s += red[w];
    float inv = 1.0f / s;
    #pragma unroll
    for (int i = 0; i < PER; i++)
        p0[tid + i * 256] = __float2half_rn(vals[i] * inv);
}

// ---------------- launch ----------------
extern "C" void kernel_launch(void* const* d_in, const int* in_sizes, int n_in,
                              void* d_out, int out_size)
{
    const float* x  = (const float*)d_in[0];
    const float* wq = (const float*)d_in[1];
    const float* wk = (const float*)d_in[2];
    const float* wv = (const float*)d_in[3];
    float* out = (float*)d_out;

    const int SM22 = 2 * 4 * TILE_BYTES;   // <2,2,1>: 64 KB
    const int SM11 = 2 * 2 * TILE_BYTES;   // <1,1,0>: 32 KB

    static bool attr_done = false;
    if (!attr_done) {
        cudaFuncSetAttribute((const void*)mma_gemm_h<2, 2, 1>,
                             cudaFuncAttributeMaxDynamicSharedMemorySize, SM22);
        cudaFuncSetAttribute((const void*)mma_gemm_h<1, 1, 0>,
                             cudaFuncAttributeMaxDynamicSharedMemorySize, SM11);
        attr_done = true;
    }

    fp16 *x0, *x1, *wq0, *wq1, *wk0, *wk1, *wv0, *wv1;
    fp16 *q0, *q1, *k0, *k1, *v0, *v1, *vT0, *w0;
    float* sc;
    cudaGetSymbolAddress((void**)&x0, g_x0);     cudaGetSymbolAddress((void**)&x1, g_x1);
    cudaGetSymbolAddress((void**)&wq0, g_wq0);   cudaGetSymbolAddress((void**)&wq1, g_wq1);
    cudaGetSymbolAddress((void**)&wk0, g_wk0);   cudaGetSymbolAddress((void**)&wk1, g_wk1);
    cudaGetSymbolAddress((void**)&wv0, g_wv0);   cudaGetSymbolAddress((void**)&wv1, g_wv1);
    cudaGetSymbolAddress((void**)&q0, g_q0);     cudaGetSymbolAddress((void**)&q1, g_q1);
    cudaGetSymbolAddress((void**)&k0, g_k0);     cudaGetSymbolAddress((void**)&k1, g_k1);
    cudaGetSymbolAddress((void**)&v0, g_v0);     cudaGetSymbolAddress((void**)&v1, g_v1);
    cudaGetSymbolAddress((void**)&vT0, g_vT0);
    cudaGetSymbolAddress((void**)&sc, g_s);
    cudaGetSymbolAddress((void**)&w0, g_w0);

    // 1) splits
    split_x<<<(M_TOT * (long)D_) / (256 * 4), 256>>>(x, x0, x1, (long)M_TOT * D_);
    dim3 tgrid(D_ / 32, D_ / 32);
    splitT2h_f32<<<tgrid, 256>>>(wq, wq0, wq1, D_, D_);
    splitT2h_f32<<<tgrid, 256>>>(wk, wk0, wk1, D_, D_);
    splitT2h_f32<<<tgrid, 256>>>(wv, wv0, wv1, D_, D_);

    // 2) fused Q+K+V projections (z selects weight/output set) -> 2-way fp16
    dim3 gQKV(D_ / GBN, M_TOT / GBM, 3);
    mma_gemm_h<2, 2, 1><<<gQKV, 256, SM22>>>(x0, x1,
                                         wq0, wq1, wk0, wk1, wv0, wv1,
                                         nullptr, q0, q1, k0, k1, v0, v1,
                                         M_TOT, D_, D_, 0, 0, 0, 1, 1);

    // 3) transpose V hi-half only: [B][S,D] -> [B][D,S]
    dim3 gT(D_ / 32, S_ / 32, B_);
    transpose_fp16<<<gT, 256>>>(v0, vT0);

    // 4) scores[b] = Q[b] * K[b]^T -> fp32   (3-term, unchanged numerics)
    dim3 gS(S_ / GBN, S_ / GBM, B_);
    mma_gemm_h<2, 2, 1><<<gS, 256, SM22>>>(q0, q1,
                                       k0, k1, nullptr, nullptr, nullptr, nullptr,
                                       sc, nullptr, nullptr, nullptr, nullptr, nullptr, nullptr,
                                       S_, S_, D_, (long)S_ * D_, (long)S_ * D_, (long)S_ * S_, 0, 0);

    // 5) softmax -> single fp16 weights
    softmax_rows<<<B_ * S_, 256>>>(sc, w0);

    // 6) out[b] = W[b] * V[b] -> fp32  (single-term fp16 x fp16)
    dim3 gO(D_ / GBN, S_ / GBM, B_);
    mma_gemm_h<1, 1, 0><<<gO, 256, SM11>>>(w0, nullptr,
                                       vT0, nullptr, nullptr, nullptr, nullptr, nullptr,
                                       out, nullptr, nullptr, nullptr, nullptr, nullptr, nullptr,
                                       S_, D_, S_, (long)S_ * S_, (long)D_ * S_, (long)S_ * D_, 0, 0);
}